// round 14
// baseline (speedup 1.0000x reference)
#include <cuda_runtime.h>
#include <cuda_fp16.h>
#include <stdint.h>

#define BATCH 4
#define SEQ   4096
#define DIM   1024
#define QKVN  3072

// CTA tile 128x128, 4 warps of 64x64, 128 threads
#define TM 128
#define TN 128
#define KC 64
#define PITCH 132   // fp32 stage pitch (V-transpose epilogue only)

#define NELT_X ((long)BATCH*SEQ*DIM)   // 16,777,216
#define NELT_W ((long)QKVN*DIM)        //  3,145,728
#define NELT_S ((long)BATCH*SEQ*SEQ)   // 67,108,864

// -------- scratch (device globals; no allocations allowed) --------
__device__ __half g_xh [NELT_X];
__device__ __half g_Wh [NELT_W];
__device__ __half g_Qh [NELT_X];
__device__ __half g_Kh [NELT_X];
__device__ __half g_Vth[NELT_X];                 // V transposed [B][DIM][SEQ]
__device__ __half g_Ph [NELT_S];                 // unnormalized exp(scores)
__device__ float  g_rowsum[(long)BATCH * SEQ];

extern __shared__ char dynsmem[];

// ---------------- helpers ----------------
__device__ __forceinline__ uint32_t cvta_smem(const void* p) {
    uint32_t a;
    asm("{ .reg .u64 t; cvta.to.shared.u64 t, %1; cvt.u32.u64 %0, t; }" : "=r"(a) : "l"(p));
    return a;
}
__device__ __forceinline__ void cp16(uint32_t s, const void* g) {
    asm volatile("cp.async.cg.shared.global [%0], [%1], 16;" :: "r"(s), "l"(g));
}
__device__ __forceinline__ void cp_commit() { asm volatile("cp.async.commit_group;" ::: "memory"); }
template <int N> __device__ __forceinline__ void cp_wait() {
    asm volatile("cp.async.wait_group %0;" :: "n"(N) : "memory");
}
__device__ __forceinline__ uint32_t swz(uint32_t off) { return off ^ ((off >> 3) & 0x70); }

__device__ __forceinline__ void ldsm4(uint32_t& r0, uint32_t& r1, uint32_t& r2, uint32_t& r3,
                                      uint32_t addr) {
    asm volatile("ldmatrix.sync.aligned.m8n8.x4.shared.b16 {%0,%1,%2,%3}, [%4];"
                 : "=r"(r0), "=r"(r1), "=r"(r2), "=r"(r3) : "r"(addr));
}
__device__ __forceinline__ void mma16816(float* c, const uint32_t* a, const uint32_t* b) {
    asm volatile(
        "mma.sync.aligned.m16n8k16.row.col.f32.f16.f16.f32 "
        "{%0,%1,%2,%3}, {%4,%5,%6,%7}, {%8,%9}, {%0,%1,%2,%3};"
        : "+f"(c[0]), "+f"(c[1]), "+f"(c[2]), "+f"(c[3])
        : "r"(a[0]), "r"(a[1]), "r"(a[2]), "r"(a[3]), "r"(b[0]), "r"(b[1]));
}

// load [128 x 64] f16 K-major tile into SW128-swizzled smem; ld = row stride (elems)
__device__ __forceinline__ void load_tile(uint32_t sb, const __half* __restrict__ src,
                                          long ld, long row0, long k0) {
    const int tid = threadIdx.x;
#pragma unroll
    for (int i = 0; i < 8; i++) {
        const int idx = tid + i * 128;        // 0..1023
        const int r = idx >> 3, ch = idx & 7;
        const uint32_t off = swz((uint32_t)(r * 128 + ch * 16));
        cp16(sb + off, src + (row0 + r) * ld + k0 + ch * 8);
    }
}

// one ks-step (16 k-depth): 8 LDSM + 32 MMA for a 64x64 warp tile
__device__ __forceinline__ void mma_step(uint32_t cur, int ks, int wm, int wn,
                                         uint32_t aPart, uint32_t bPart,
                                         float acc[4][8][4]) {
    const uint32_t OA = 0, OB = 16 * 1024;
    uint32_t ah[4][4], bh[4][4];
#pragma unroll
    for (int mt = 0; mt < 4; ++mt) {
        const uint32_t off = (uint32_t)((wm * 64 + mt * 16) * 128 + ks * 32) + aPart;
        ldsm4(ah[mt][0], ah[mt][1], ah[mt][2], ah[mt][3], cur + OA + swz(off));
    }
#pragma unroll
    for (int nt = 0; nt < 4; ++nt) {
        const uint32_t off = (uint32_t)((wn * 64 + nt * 16) * 128 + ks * 32) + bPart;
        ldsm4(bh[nt][0], bh[nt][1], bh[nt][2], bh[nt][3], cur + OB + swz(off));
    }
#pragma unroll
    for (int mt = 0; mt < 4; ++mt)
#pragma unroll
        for (int nt = 0; nt < 4; ++nt) {
            mma16816(acc[mt][nt * 2],     ah[mt], &bh[nt][0]);
            mma16816(acc[mt][nt * 2 + 1], ah[mt], &bh[nt][2]);
        }
}

// ----------------------------------------------------------------------------
// gemm1: C[128,128] = Ah * Bh^T (single f16), 4 warps of 64x64, 3-stage pipeline.
// ld = row stride of both operands (elements); Kcnt = K-depth to accumulate.
// ----------------------------------------------------------------------------
__device__ __forceinline__ void gemm1(const __half* __restrict__ Ah,
                                      const __half* __restrict__ Bh,
                                      long bm, long bn, long ld, int Kcnt,
                                      float acc[4][8][4]) {
    const uint32_t STAGE = 32 * 1024;
    const uint32_t OA = 0, OB = 16 * 1024;
    const uint32_t smb = cvta_smem(dynsmem);
    const int wid = threadIdx.x >> 5, lane = threadIdx.x & 31;
    const int wm = wid & 1, wn = wid >> 1;
    const int NIT = Kcnt / KC;

#pragma unroll
    for (int i = 0; i < 4; i++)
#pragma unroll
        for (int j = 0; j < 8; j++)
#pragma unroll
            for (int k = 0; k < 4; k++) acc[i][j][k] = 0.0f;

    const uint32_t aPart = (uint32_t)((lane & 15) * 128 + (lane >> 4) * 16);
    const uint32_t bPart = (uint32_t)((((lane & 7) + ((lane >> 4) << 3)) * 128) + ((lane >> 3) & 1) * 16);

    // prologue: stages 0,1 -> groups 0,1
    load_tile(smb + 0 * STAGE + OA, Ah, ld, bm, 0);
    load_tile(smb + 0 * STAGE + OB, Bh, ld, bn, 0);
    cp_commit();
    load_tile(smb + 1 * STAGE + OA, Ah, ld, bm, KC);
    load_tile(smb + 1 * STAGE + OB, Bh, ld, bn, KC);
    cp_commit();

    int stg = 0, nstg = 2;
    for (int it = 0; it < NIT; ++it) {
        cp_wait<1>();
        __syncthreads();
        const uint32_t cur = smb + (uint32_t)stg * STAGE;

        mma_step(cur, 0, wm, wn, aPart, bPart, acc);

        if (it + 2 < NIT) {
            const uint32_t nb = smb + (uint32_t)nstg * STAGE;
            const long k0 = (long)(it + 2) * KC;
            load_tile(nb + OA, Ah, ld, bm, k0);
            load_tile(nb + OB, Bh, ld, bn, k0);
        }
        cp_commit();

#pragma unroll
        for (int ks = 1; ks < KC / 16; ++ks)
            mma_step(cur, ks, wm, wn, aPart, bPart, acc);

        stg = (stg == 2) ? 0 : stg + 1;
        nstg = (nstg == 2) ? 0 : nstg + 1;
    }
}

// dump accs to fp32 smem stage — used only by the V-transpose epilogue
__device__ __forceinline__ void acc_to_stage(float acc[4][8][4]) {
    __syncthreads();
    float* stage = (float*)dynsmem;
    const int wid = threadIdx.x >> 5, lane = threadIdx.x & 31;
    const int wm = wid & 1, wn = wid >> 1;
    const int rl = lane >> 2, cl = (lane & 3) * 2;
#pragma unroll
    for (int mt = 0; mt < 4; ++mt)
#pragma unroll
        for (int n8 = 0; n8 < 8; ++n8) {
            const int r = wm * 64 + mt * 16 + rl;
            const int c = wn * 64 + n8 * 8 + cl;
            *(float2*)&stage[r * PITCH + c] = make_float2(acc[mt][n8][0], acc[mt][n8][1]);
            *(float2*)&stage[(r + 8) * PITCH + c] = make_float2(acc[mt][n8][2], acc[mt][n8][3]);
        }
    __syncthreads();
}

// ---------------- merged setup: convert x, convert W, zero rowsum, zero out ----------------
#define XBLKS (NELT_X / 1024)          // 16384
#define WBLKS (NELT_W / 1024)          // 3072
#define ZBLKS ((BATCH * SEQ) / 256)    // 64
#define OBLKS (NELT_X / 1024)          // 16384 (out has NELT_X elements)
__global__ void __launch_bounds__(256) setup_kernel(const float* __restrict__ x1,
                                                    const float* __restrict__ W,
                                                    float* __restrict__ out) {
    const long b = blockIdx.x;
    if (b < XBLKS + WBLKS) {
        const float* in = (b < XBLKS) ? x1 : W;
        __half* dst = (b < XBLKS) ? g_xh : g_Wh;
        const long i = ((b < XBLKS) ? b : b - XBLKS) * 256 + threadIdx.x;
        float4 v = ((const float4*)in)[i];
        __half2 a2, b2;
        a2.x = __float2half_rn(v.x); a2.y = __float2half_rn(v.y);
        b2.x = __float2half_rn(v.z); b2.y = __float2half_rn(v.w);
        uint2 o;
        o.x = *reinterpret_cast<uint32_t*>(&a2);
        o.y = *reinterpret_cast<uint32_t*>(&b2);
        *(uint2*)(dst + i * 4) = o;
    } else if (b < XBLKS + WBLKS + ZBLKS) {
        g_rowsum[(b - XBLKS - WBLKS) * 256 + threadIdx.x] = 0.0f;
    } else {
        const long i = (b - XBLKS - WBLKS - ZBLKS) * 256 + threadIdx.x;
        ((float4*)out)[i] = make_float4(0.f, 0.f, 0.f, 0.f);
    }
}

// ---------------- Kernel 1: QKV projection ----------------
__global__ void __launch_bounds__(128, 2) qkv_gemm_tc(const float* __restrict__ bias) {
    const long bm = (long)blockIdx.y * TM;
    const long bn = (long)blockIdx.x * TN;
    float acc[4][8][4];
    gemm1(g_xh, g_Wh, bm, bn, DIM, DIM, acc);

    const int sel = (int)(bn >> 10);        // 0:Q 1:K 2:V
    const long nc0 = bn & 1023;
    const int wid = threadIdx.x >> 5, lane = threadIdx.x & 31;
    const int wm = wid & 1, wn = wid >> 1;
    const int rl = lane >> 2, cl = (lane & 3) * 2;

    if (sel < 2) {
        __half* dst = sel ? g_Kh : g_Qh;
#pragma unroll
        for (int mt = 0; mt < 4; ++mt) {
            const long ra = bm + wm * 64 + mt * 16 + rl;
#pragma unroll
            for (int n8 = 0; n8 < 8; ++n8) {
                const int c = wn * 64 + n8 * 8 + cl;
                const float b0 = bias[bn + c], b1 = bias[bn + c + 1];
                __half2 H0, H1;
                H0.x = __float2half_rn(acc[mt][n8][0] + b0);
                H0.y = __float2half_rn(acc[mt][n8][1] + b1);
                H1.x = __float2half_rn(acc[mt][n8][2] + b0);
                H1.y = __float2half_rn(acc[mt][n8][3] + b1);
                *(__half2*)(dst + ra * DIM + nc0 + c) = H0;
                *(__half2*)(dst + (ra + 8) * DIM + nc0 + c) = H1;
            }
        }
    } else {
        acc_to_stage(acc);
        float* stage = (float*)dynsmem;
        const long b = bm >> 12, s0 = bm & 4095;
        for (int idx = threadIdx.x; idx < TM * TN; idx += 128) {
            const int row = idx & 127, col = idx >> 7;
            const float v = stage[row * PITCH + col] + bias[bn + col];
            g_Vth[(b * DIM + nc0 + col) * SEQ + s0 + row] = __float2half_rn(v);
        }
    }
}

// ---------------- Kernel 2: P̂ = exp((Q K^T)/32) — full register epilogue ----------------
__global__ void __launch_bounds__(128, 2) scores_gemm_tc() {
    const int z = blockIdx.z;
    const long bm = (long)blockIdx.y * TM;
    const long bn = (long)blockIdx.x * TN;
    const long qo = (long)z * SEQ * DIM;
    float acc[4][8][4];
    gemm1(g_Qh + qo, g_Kh + qo, bm, bn, DIM, DIM, acc);

#pragma unroll
    for (int mt = 0; mt < 4; ++mt)
#pragma unroll
        for (int n8 = 0; n8 < 8; ++n8)
#pragma unroll
            for (int k = 0; k < 4; ++k)
                acc[mt][n8][k] = __expf(acc[mt][n8][k] * 0.03125f);

    const long so = (long)z * SEQ * SEQ;
    const int wid = threadIdx.x >> 5, lane = threadIdx.x & 31;
    const int wm = wid & 1, wn = wid >> 1;
    const int rl = lane >> 2, cl = (lane & 3) * 2;
    float* rsbase = g_rowsum + (long)z * SEQ;

#pragma unroll
    for (int mt = 0; mt < 4; ++mt) {
        const long ra = bm + wm * 64 + mt * 16 + rl;
        float s0 = 0.0f, s1 = 0.0f;
#pragma unroll
        for (int n8 = 0; n8 < 8; ++n8) {
            const int c = wn * 64 + n8 * 8 + cl;
            __half2 H0, H1;
            H0.x = __float2half_rn(acc[mt][n8][0]);
            H0.y = __float2half_rn(acc[mt][n8][1]);
            H1.x = __float2half_rn(acc[mt][n8][2]);
            H1.y = __float2half_rn(acc[mt][n8][3]);
            *(__half2*)(g_Ph + so + ra * SEQ + bn + c) = H0;
            *(__half2*)(g_Ph + so + (ra + 8) * SEQ + bn + c) = H1;
            s0 += acc[mt][n8][0] + acc[mt][n8][1];
            s1 += acc[mt][n8][2] + acc[mt][n8][3];
        }
        s0 += __shfl_xor_sync(0xffffffffu, s0, 1);
        s0 += __shfl_xor_sync(0xffffffffu, s0, 2);
        s1 += __shfl_xor_sync(0xffffffffu, s1, 1);
        s1 += __shfl_xor_sync(0xffffffffu, s1, 2);
        if ((lane & 3) == 0) {
            atomicAdd(&rsbase[ra], s0);
            atomicAdd(&rsbase[ra + 8], s1);
        }
    }
}

// ---------------- Kernel 3: out += (P̂_half @ V_half)/rowsum — split-K x2 ----------------
// blockIdx.x encodes (n-tile, k-half): n = x >> 1, kh = x & 1.
// Each half scales by 1/rowsum (division is linear) and fp32-atomicAdds into out.
// Exactly 2 addends per element; fp add is commutative -> deterministic.
__global__ void __launch_bounds__(128, 2) pv_gemm_tc(float* __restrict__ out) {
    const int z = blockIdx.z;
    const long bm = (long)blockIdx.y * TM;
    const long bn = (long)(blockIdx.x >> 1) * TN;
    const long kh = (long)(blockIdx.x & 1) * (SEQ / 2);
    const long po = (long)z * SEQ * SEQ;
    const long vo = (long)z * DIM * SEQ;
    float acc[4][8][4];
    gemm1(g_Ph + po + kh, g_Vth + vo + kh, bm, bn, SEQ, SEQ / 2, acc);

    float* O = out + (long)z * SEQ * DIM;
    const float* rs = g_rowsum + (long)z * SEQ;
    const int wid = threadIdx.x >> 5, lane = threadIdx.x & 31;
    const int wm = wid & 1, wn = wid >> 1;
    const int rl = lane >> 2, cl = (lane & 3) * 2;
#pragma unroll
    for (int mt = 0; mt < 4; ++mt) {
        const long ra = bm + wm * 64 + mt * 16 + rl;
        const float ia = 1.0f / rs[ra];
        const float ib = 1.0f / rs[ra + 8];
#pragma unroll
        for (int n8 = 0; n8 < 8; ++n8) {
            const long c = bn + wn * 64 + n8 * 8 + cl;
            atomicAdd(&O[ra * DIM + c],           acc[mt][n8][0] * ia);
            atomicAdd(&O[ra * DIM + c + 1],       acc[mt][n8][1] * ia);
            atomicAdd(&O[(ra + 8) * DIM + c],     acc[mt][n8][2] * ib);
            atomicAdd(&O[(ra + 8) * DIM + c + 1], acc[mt][n8][3] * ib);
        }
    }
}

// ---------------------------------------------------------------------------
extern "C" void kernel_launch(void* const* d_in, const int* in_sizes, int n_in,
                              void* d_out, int out_size) {
    const float* x1 = nullptr;
    const float* W = nullptr;
    const float* bias = nullptr;
    for (int i = 0; i < n_in; i++) {
        if (in_sizes[i] == (int)(BATCH * SEQ * DIM)) x1 = (const float*)d_in[i];
        else if (in_sizes[i] == (int)(QKVN * DIM))   W = (const float*)d_in[i];
        else if (in_sizes[i] == QKVN)                bias = (const float*)d_in[i];
    }
    float* out = (float*)d_out;

    const int SM_BYTES = 96 * 1024;   // 3 x 32KB stages; fp32 stage overlay 67.6KB

    cudaFuncSetAttribute(qkv_gemm_tc, cudaFuncAttributeMaxDynamicSharedMemorySize, SM_BYTES);
    cudaFuncSetAttribute(scores_gemm_tc, cudaFuncAttributeMaxDynamicSharedMemorySize, SM_BYTES);
    cudaFuncSetAttribute(pv_gemm_tc, cudaFuncAttributeMaxDynamicSharedMemorySize, SM_BYTES);

    setup_kernel<<<XBLKS + WBLKS + ZBLKS + OBLKS, 256>>>(x1, W, out);
    qkv_gemm_tc<<<dim3(QKVN / TN, (BATCH * SEQ) / TM), 128, SM_BYTES>>>(bias);
    scores_gemm_tc<<<dim3(SEQ / TN, SEQ / TM, BATCH), 128, SM_BYTES>>>();
    pv_gemm_tc<<<dim3((DIM / TN) * 2, SEQ / TM, BATCH), 128, SM_BYTES>>>(out);
}

// round 15
// speedup vs baseline: 1.0309x; 1.0309x over previous
#include <cuda_runtime.h>
#include <cuda_fp16.h>
#include <stdint.h>

#define BATCH 4
#define SEQ   4096
#define DIM   1024
#define QKVN  3072

// CTA tile 128x128, 4 warps of 64x64, 128 threads
#define TM 128
#define TN 128
#define KC 64
#define PITCH 132   // fp32 stage pitch (V-transpose epilogue only)

#define NELT_X ((long)BATCH*SEQ*DIM)   // 16,777,216
#define NELT_W ((long)QKVN*DIM)        //  3,145,728
#define NELT_S ((long)BATCH*SEQ*SEQ)   // 67,108,864

// -------- scratch (device globals; no allocations allowed) --------
__device__ __half g_xh [NELT_X];
__device__ __half g_Wh [NELT_W];
__device__ __half g_Qh [NELT_X];
__device__ __half g_Kh [NELT_X];
__device__ __half g_Vth[NELT_X];                 // V transposed [B][DIM][SEQ]
__device__ __half g_Ph [NELT_S];                 // unnormalized exp(scores)
__device__ float  g_rowsum[(long)BATCH * SEQ];

extern __shared__ char dynsmem[];

// ---------------- helpers ----------------
__device__ __forceinline__ uint32_t cvta_smem(const void* p) {
    uint32_t a;
    asm("{ .reg .u64 t; cvta.to.shared.u64 t, %1; cvt.u32.u64 %0, t; }" : "=r"(a) : "l"(p));
    return a;
}
__device__ __forceinline__ void cp16(uint32_t s, const void* g) {
    asm volatile("cp.async.cg.shared.global [%0], [%1], 16;" :: "r"(s), "l"(g));
}
__device__ __forceinline__ void cp_commit() { asm volatile("cp.async.commit_group;" ::: "memory"); }
template <int N> __device__ __forceinline__ void cp_wait() {
    asm volatile("cp.async.wait_group %0;" :: "n"(N) : "memory");
}
__device__ __forceinline__ uint32_t swz(uint32_t off) { return off ^ ((off >> 3) & 0x70); }

__device__ __forceinline__ void ldsm4(uint32_t& r0, uint32_t& r1, uint32_t& r2, uint32_t& r3,
                                      uint32_t addr) {
    asm volatile("ldmatrix.sync.aligned.m8n8.x4.shared.b16 {%0,%1,%2,%3}, [%4];"
                 : "=r"(r0), "=r"(r1), "=r"(r2), "=r"(r3) : "r"(addr));
}
__device__ __forceinline__ void mma16816(float* c, const uint32_t* a, const uint32_t* b) {
    asm volatile(
        "mma.sync.aligned.m16n8k16.row.col.f32.f16.f16.f32 "
        "{%0,%1,%2,%3}, {%4,%5,%6,%7}, {%8,%9}, {%0,%1,%2,%3};"
        : "+f"(c[0]), "+f"(c[1]), "+f"(c[2]), "+f"(c[3])
        : "r"(a[0]), "r"(a[1]), "r"(a[2]), "r"(a[3]), "r"(b[0]), "r"(b[1]));
}

// load [128 x 64] f16 K-major tile into SW128-swizzled smem; ld = row stride (elems)
__device__ __forceinline__ void load_tile(uint32_t sb, const __half* __restrict__ src,
                                          long ld, long row0, long k0) {
    const int tid = threadIdx.x;
#pragma unroll
    for (int i = 0; i < 8; i++) {
        const int idx = tid + i * 128;        // 0..1023
        const int r = idx >> 3, ch = idx & 7;
        const uint32_t off = swz((uint32_t)(r * 128 + ch * 16));
        cp16(sb + off, src + (row0 + r) * ld + k0 + ch * 8);
    }
}

// one ks-step (16 k-depth), interleaved: load B frags, then per-mt load A frag
// and immediately issue its 8 MMAs — LDSM for mt+1 overlaps mt's MMA burst,
// and peak live fragments drop 32 -> 20 regs.
__device__ __forceinline__ void mma_step(uint32_t cur, int ks, int wm, int wn,
                                         uint32_t aPart, uint32_t bPart,
                                         float acc[4][8][4]) {
    const uint32_t OA = 0, OB = 16 * 1024;
    uint32_t bh[4][4];
#pragma unroll
    for (int nt = 0; nt < 4; ++nt) {
        const uint32_t off = (uint32_t)((wn * 64 + nt * 16) * 128 + ks * 32) + bPart;
        ldsm4(bh[nt][0], bh[nt][1], bh[nt][2], bh[nt][3], cur + OB + swz(off));
    }
#pragma unroll
    for (int mt = 0; mt < 4; ++mt) {
        uint32_t ah[4];
        const uint32_t off = (uint32_t)((wm * 64 + mt * 16) * 128 + ks * 32) + aPart;
        ldsm4(ah[0], ah[1], ah[2], ah[3], cur + OA + swz(off));
#pragma unroll
        for (int nt = 0; nt < 4; ++nt) {
            mma16816(acc[mt][nt * 2],     ah, &bh[nt][0]);
            mma16816(acc[mt][nt * 2 + 1], ah, &bh[nt][2]);
        }
    }
}

// ----------------------------------------------------------------------------
// gemm1: C[128,128] = Ah * Bh^T (single f16), 4 warps of 64x64, 3-stage pipeline.
// ld = row stride of both operands (elements); Kcnt = K-depth to accumulate.
// k-loop: wait; sync; [ks=0 MMA]; issue loads(it+2); commit; [ks=1..3].
// ----------------------------------------------------------------------------
__device__ __forceinline__ void gemm1(const __half* __restrict__ Ah,
                                      const __half* __restrict__ Bh,
                                      long bm, long bn, long ld, int Kcnt,
                                      float acc[4][8][4]) {
    const uint32_t STAGE = 32 * 1024;
    const uint32_t OA = 0, OB = 16 * 1024;
    const uint32_t smb = cvta_smem(dynsmem);
    const int wid = threadIdx.x >> 5, lane = threadIdx.x & 31;
    const int wm = wid & 1, wn = wid >> 1;
    const int NIT = Kcnt / KC;

#pragma unroll
    for (int i = 0; i < 4; i++)
#pragma unroll
        for (int j = 0; j < 8; j++)
#pragma unroll
            for (int k = 0; k < 4; k++) acc[i][j][k] = 0.0f;

    const uint32_t aPart = (uint32_t)((lane & 15) * 128 + (lane >> 4) * 16);
    const uint32_t bPart = (uint32_t)((((lane & 7) + ((lane >> 4) << 3)) * 128) + ((lane >> 3) & 1) * 16);

    // prologue: stages 0,1 -> groups 0,1
    load_tile(smb + 0 * STAGE + OA, Ah, ld, bm, 0);
    load_tile(smb + 0 * STAGE + OB, Bh, ld, bn, 0);
    cp_commit();
    load_tile(smb + 1 * STAGE + OA, Ah, ld, bm, KC);
    load_tile(smb + 1 * STAGE + OB, Bh, ld, bn, KC);
    cp_commit();

    int stg = 0, nstg = 2;
    for (int it = 0; it < NIT; ++it) {
        cp_wait<1>();
        __syncthreads();
        const uint32_t cur = smb + (uint32_t)stg * STAGE;

        mma_step(cur, 0, wm, wn, aPart, bPart, acc);

        if (it + 2 < NIT) {
            const uint32_t nb = smb + (uint32_t)nstg * STAGE;
            const long k0 = (long)(it + 2) * KC;
            load_tile(nb + OA, Ah, ld, bm, k0);
            load_tile(nb + OB, Bh, ld, bn, k0);
        }
        cp_commit();

#pragma unroll
        for (int ks = 1; ks < KC / 16; ++ks)
            mma_step(cur, ks, wm, wn, aPart, bPart, acc);

        stg = (stg == 2) ? 0 : stg + 1;
        nstg = (nstg == 2) ? 0 : nstg + 1;
    }
}

// dump accs to fp32 smem stage — used only by the V-transpose epilogue
__device__ __forceinline__ void acc_to_stage(float acc[4][8][4]) {
    __syncthreads();
    float* stage = (float*)dynsmem;
    const int wid = threadIdx.x >> 5, lane = threadIdx.x & 31;
    const int wm = wid & 1, wn = wid >> 1;
    const int rl = lane >> 2, cl = (lane & 3) * 2;
#pragma unroll
    for (int mt = 0; mt < 4; ++mt)
#pragma unroll
        for (int n8 = 0; n8 < 8; ++n8) {
            const int r = wm * 64 + mt * 16 + rl;
            const int c = wn * 64 + n8 * 8 + cl;
            *(float2*)&stage[r * PITCH + c] = make_float2(acc[mt][n8][0], acc[mt][n8][1]);
            *(float2*)&stage[(r + 8) * PITCH + c] = make_float2(acc[mt][n8][2], acc[mt][n8][3]);
        }
    __syncthreads();
}

// ---------------- merged setup: convert x, convert W, zero rowsum ----------------
#define XBLKS (NELT_X / 1024)          // 16384
#define WBLKS (NELT_W / 1024)          // 3072
#define ZBLKS ((BATCH * SEQ) / 256)    // 64
__global__ void __launch_bounds__(256) setup_kernel(const float* __restrict__ x1,
                                                    const float* __restrict__ W) {
    const long b = blockIdx.x;
    if (b < XBLKS + WBLKS) {
        const float* in = (b < XBLKS) ? x1 : W;
        __half* dst = (b < XBLKS) ? g_xh : g_Wh;
        const long i = ((b < XBLKS) ? b : b - XBLKS) * 256 + threadIdx.x;
        float4 v = ((const float4*)in)[i];
        __half2 a2, b2;
        a2.x = __float2half_rn(v.x); a2.y = __float2half_rn(v.y);
        b2.x = __float2half_rn(v.z); b2.y = __float2half_rn(v.w);
        uint2 o;
        o.x = *reinterpret_cast<uint32_t*>(&a2);
        o.y = *reinterpret_cast<uint32_t*>(&b2);
        *(uint2*)(dst + i * 4) = o;
    } else {
        g_rowsum[(b - XBLKS - WBLKS) * 256 + threadIdx.x] = 0.0f;
    }
}

// ---------------- Kernel 1: QKV projection ----------------
__global__ void __launch_bounds__(128, 2) qkv_gemm_tc(const float* __restrict__ bias) {
    const long bm = (long)blockIdx.y * TM;
    const long bn = (long)blockIdx.x * TN;
    float acc[4][8][4];
    gemm1(g_xh, g_Wh, bm, bn, DIM, DIM, acc);

    const int sel = (int)(bn >> 10);        // 0:Q 1:K 2:V
    const long nc0 = bn & 1023;
    const int wid = threadIdx.x >> 5, lane = threadIdx.x & 31;
    const int wm = wid & 1, wn = wid >> 1;
    const int rl = lane >> 2, cl = (lane & 3) * 2;

    if (sel < 2) {
        __half* dst = sel ? g_Kh : g_Qh;
#pragma unroll
        for (int mt = 0; mt < 4; ++mt) {
            const long ra = bm + wm * 64 + mt * 16 + rl;
#pragma unroll
            for (int n8 = 0; n8 < 8; ++n8) {
                const int c = wn * 64 + n8 * 8 + cl;
                const float b0 = bias[bn + c], b1 = bias[bn + c + 1];
                __half2 H0, H1;
                H0.x = __float2half_rn(acc[mt][n8][0] + b0);
                H0.y = __float2half_rn(acc[mt][n8][1] + b1);
                H1.x = __float2half_rn(acc[mt][n8][2] + b0);
                H1.y = __float2half_rn(acc[mt][n8][3] + b1);
                *(__half2*)(dst + ra * DIM + nc0 + c) = H0;
                *(__half2*)(dst + (ra + 8) * DIM + nc0 + c) = H1;
            }
        }
    } else {
        acc_to_stage(acc);
        float* stage = (float*)dynsmem;
        const long b = bm >> 12, s0 = bm & 4095;
        for (int idx = threadIdx.x; idx < TM * TN; idx += 128) {
            const int row = idx & 127, col = idx >> 7;
            const float v = stage[row * PITCH + col] + bias[bn + col];
            g_Vth[(b * DIM + nc0 + col) * SEQ + s0 + row] = __float2half_rn(v);
        }
    }
}

// ---------------- Kernel 2: P̂ = exp((Q K^T)/32) — full register epilogue ----------------
__global__ void __launch_bounds__(128, 2) scores_gemm_tc() {
    const int z = blockIdx.z;
    const long bm = (long)blockIdx.y * TM;
    const long bn = (long)blockIdx.x * TN;
    const long qo = (long)z * SEQ * DIM;
    float acc[4][8][4];
    gemm1(g_Qh + qo, g_Kh + qo, bm, bn, DIM, DIM, acc);

#pragma unroll
    for (int mt = 0; mt < 4; ++mt)
#pragma unroll
        for (int n8 = 0; n8 < 8; ++n8)
#pragma unroll
            for (int k = 0; k < 4; ++k)
                acc[mt][n8][k] = __expf(acc[mt][n8][k] * 0.03125f);

    const long so = (long)z * SEQ * SEQ;
    const int wid = threadIdx.x >> 5, lane = threadIdx.x & 31;
    const int wm = wid & 1, wn = wid >> 1;
    const int rl = lane >> 2, cl = (lane & 3) * 2;
    float* rsbase = g_rowsum + (long)z * SEQ;

#pragma unroll
    for (int mt = 0; mt < 4; ++mt) {
        const long ra = bm + wm * 64 + mt * 16 + rl;
        float s0 = 0.0f, s1 = 0.0f;
#pragma unroll
        for (int n8 = 0; n8 < 8; ++n8) {
            const int c = wn * 64 + n8 * 8 + cl;
            __half2 H0, H1;
            H0.x = __float2half_rn(acc[mt][n8][0]);
            H0.y = __float2half_rn(acc[mt][n8][1]);
            H1.x = __float2half_rn(acc[mt][n8][2]);
            H1.y = __float2half_rn(acc[mt][n8][3]);
            *(__half2*)(g_Ph + so + ra * SEQ + bn + c) = H0;
            *(__half2*)(g_Ph + so + (ra + 8) * SEQ + bn + c) = H1;
            s0 += acc[mt][n8][0] + acc[mt][n8][1];
            s1 += acc[mt][n8][2] + acc[mt][n8][3];
        }
        s0 += __shfl_xor_sync(0xffffffffu, s0, 1);
        s0 += __shfl_xor_sync(0xffffffffu, s0, 2);
        s1 += __shfl_xor_sync(0xffffffffu, s1, 1);
        s1 += __shfl_xor_sync(0xffffffffu, s1, 2);
        if ((lane & 3) == 0) {
            atomicAdd(&rsbase[ra], s0);
            atomicAdd(&rsbase[ra + 8], s1);
        }
    }
}

// ---------------- Kernel 3: out = (P̂ @ V) / rowsum — register epilogue ----------------
__global__ void __launch_bounds__(128, 2) pv_gemm_tc(float* __restrict__ out) {
    const int z = blockIdx.z;
    const long bm = (long)blockIdx.y * TM;
    const long bn = (long)blockIdx.x * TN;
    const long po = (long)z * SEQ * SEQ;
    const long vo = (long)z * DIM * SEQ;
    float acc[4][8][4];
    gemm1(g_Ph + po, g_Vth + vo, bm, bn, SEQ, SEQ, acc);

    float* O = out + (long)z * SEQ * DIM;
    const float* rs = g_rowsum + (long)z * SEQ;
    const int wid = threadIdx.x >> 5, lane = threadIdx.x & 31;
    const int wm = wid & 1, wn = wid >> 1;
    const int rl = lane >> 2, cl = (lane & 3) * 2;
#pragma unroll
    for (int mt = 0; mt < 4; ++mt) {
        const long ra = bm + wm * 64 + mt * 16 + rl;
        const float ia = 1.0f / rs[ra];
        const float ib = 1.0f / rs[ra + 8];
#pragma unroll
        for (int n8 = 0; n8 < 8; ++n8) {
            const long c = bn + wn * 64 + n8 * 8 + cl;
            *(float2*)&O[ra * DIM + c] = make_float2(acc[mt][n8][0] * ia, acc[mt][n8][1] * ia);
            *(float2*)&O[(ra + 8) * DIM + c] = make_float2(acc[mt][n8][2] * ib, acc[mt][n8][3] * ib);
        }
    }
}

// ---------------------------------------------------------------------------
extern "C" void kernel_launch(void* const* d_in, const int* in_sizes, int n_in,
                              void* d_out, int out_size) {
    const float* x1 = nullptr;
    const float* W = nullptr;
    const float* bias = nullptr;
    for (int i = 0; i < n_in; i++) {
        if (in_sizes[i] == (int)(BATCH * SEQ * DIM)) x1 = (const float*)d_in[i];
        else if (in_sizes[i] == (int)(QKVN * DIM))   W = (const float*)d_in[i];
        else if (in_sizes[i] == QKVN)                bias = (const float*)d_in[i];
    }
    float* out = (float*)d_out;

    const int SM_BYTES = 96 * 1024;   // 3 x 32KB stages; fp32 stage overlay 67.6KB

    cudaFuncSetAttribute(qkv_gemm_tc, cudaFuncAttributeMaxDynamicSharedMemorySize, SM_BYTES);
    cudaFuncSetAttribute(scores_gemm_tc, cudaFuncAttributeMaxDynamicSharedMemorySize, SM_BYTES);
    cudaFuncSetAttribute(pv_gemm_tc, cudaFuncAttributeMaxDynamicSharedMemorySize, SM_BYTES);

    setup_kernel<<<XBLKS + WBLKS + ZBLKS, 256>>>(x1, W);
    qkv_gemm_tc<<<dim3(QKVN / TN, (BATCH * SEQ) / TM), 128, SM_BYTES>>>(bias);
    scores_gemm_tc<<<dim3(SEQ / TN, SEQ / TM, BATCH), 128, SM_BYTES>>>();
    pv_gemm_tc<<<dim3(DIM / TN, SEQ / TM, BATCH), 128, SM_BYTES>>>(out);
}

// round 16
// speedup vs baseline: 1.0326x; 1.0017x over previous
#include <cuda_runtime.h>
#include <cuda_fp16.h>
#include <stdint.h>

#define BATCH 4
#define SEQ   4096
#define DIM   1024
#define QKVN  3072

// CTA tile 128x128, 4 warps of 64x64, 128 threads
#define TM 128
#define TN 128
#define KC 64
#define PITCH 132   // fp32 stage pitch (V-transpose epilogue only)

#define NELT_X ((long)BATCH*SEQ*DIM)   // 16,777,216
#define NELT_W ((long)QKVN*DIM)        //  3,145,728
#define NELT_S ((long)BATCH*SEQ*SEQ)   // 67,108,864

// -------- scratch (device globals; no allocations allowed) --------
__device__ __half g_xh [NELT_X];
__device__ __half g_Wh [NELT_W];
__device__ __half g_Qh [NELT_X];
__device__ __half g_Kh [NELT_X];
__device__ __half g_Vth[NELT_X];                 // V transposed [B][DIM][SEQ]
__device__ __half g_Ph [NELT_S];                 // unnormalized exp(scores)
__device__ float  g_rowsum[(long)BATCH * SEQ];

extern __shared__ char dynsmem[];

// ---------------- helpers ----------------
__device__ __forceinline__ uint32_t cvta_smem(const void* p) {
    uint32_t a;
    asm("{ .reg .u64 t; cvta.to.shared.u64 t, %1; cvt.u32.u64 %0, t; }" : "=r"(a) : "l"(p));
    return a;
}
__device__ __forceinline__ void cp16(uint32_t s, const void* g) {
    asm volatile("cp.async.cg.shared.global [%0], [%1], 16;" :: "r"(s), "l"(g));
}
__device__ __forceinline__ void cp_commit() { asm volatile("cp.async.commit_group;" ::: "memory"); }
template <int N> __device__ __forceinline__ void cp_wait() {
    asm volatile("cp.async.wait_group %0;" :: "n"(N) : "memory");
}
__device__ __forceinline__ uint32_t swz(uint32_t off) { return off ^ ((off >> 3) & 0x70); }

__device__ __forceinline__ void ldsm4(uint32_t& r0, uint32_t& r1, uint32_t& r2, uint32_t& r3,
                                      uint32_t addr) {
    asm volatile("ldmatrix.sync.aligned.m8n8.x4.shared.b16 {%0,%1,%2,%3}, [%4];"
                 : "=r"(r0), "=r"(r1), "=r"(r2), "=r"(r3) : "r"(addr));
}
__device__ __forceinline__ void mma16816(float* c, const uint32_t* a, const uint32_t* b) {
    asm volatile(
        "mma.sync.aligned.m16n8k16.row.col.f32.f16.f16.f32 "
        "{%0,%1,%2,%3}, {%4,%5,%6,%7}, {%8,%9}, {%0,%1,%2,%3};"
        : "+f"(c[0]), "+f"(c[1]), "+f"(c[2]), "+f"(c[3])
        : "r"(a[0]), "r"(a[1]), "r"(a[2]), "r"(a[3]), "r"(b[0]), "r"(b[1]));
}

// load [128 x 64] f16 K-major tile into SW128-swizzled smem; ld = row stride (elems)
__device__ __forceinline__ void load_tile(uint32_t sb, const __half* __restrict__ src,
                                          long ld, long row0, long k0) {
    const int tid = threadIdx.x;
#pragma unroll
    for (int i = 0; i < 8; i++) {
        const int idx = tid + i * 128;        // 0..1023
        const int r = idx >> 3, ch = idx & 7;
        const uint32_t off = swz((uint32_t)(r * 128 + ch * 16));
        cp16(sb + off, src + (row0 + r) * ld + k0 + ch * 8);
    }
}

// load the 4 B fragments for one ks-step
__device__ __forceinline__ void load_bh(uint32_t cur, int ks, int wn, uint32_t bPart,
                                        uint32_t bh[4][4]) {
    const uint32_t OB = 16 * 1024;
#pragma unroll
    for (int nt = 0; nt < 4; ++nt) {
        const uint32_t off = (uint32_t)((wn * 64 + nt * 16) * 128 + ks * 32) + bPart;
        ldsm4(bh[nt][0], bh[nt][1], bh[nt][2], bh[nt][3], cur + OB + swz(off));
    }
}

// MMA burst for one ks-step using preloaded B frags; A frags loaded per-mt inline
__device__ __forceinline__ void mma_burst(uint32_t cur, int ks, int wm, uint32_t aPart,
                                          uint32_t bh[4][4], float acc[4][8][4]) {
    const uint32_t OA = 0;
#pragma unroll
    for (int mt = 0; mt < 4; ++mt) {
        uint32_t ah[4];
        const uint32_t off = (uint32_t)((wm * 64 + mt * 16) * 128 + ks * 32) + aPart;
        ldsm4(ah[0], ah[1], ah[2], ah[3], cur + OA + swz(off));
#pragma unroll
        for (int nt = 0; nt < 4; ++nt) {
            mma16816(acc[mt][nt * 2],     ah, &bh[nt][0]);
            mma16816(acc[mt][nt * 2 + 1], ah, &bh[nt][2]);
        }
    }
}

// ----------------------------------------------------------------------------
// gemm1: C[128,128] = Ah * Bh^T (single f16), 4 warps of 64x64, 3-stage pipeline.
// B fragments ping-pong across ks-steps: ks+1's LDSMs issue before ks's MMAs,
// hiding LDSM latency under the 32-MMA burst. Global loads(it+2) issue after
// the ks=0 burst.
// ----------------------------------------------------------------------------
__device__ __forceinline__ void gemm1(const __half* __restrict__ Ah,
                                      const __half* __restrict__ Bh,
                                      long bm, long bn, long ld, int Kcnt,
                                      float acc[4][8][4]) {
    const uint32_t STAGE = 32 * 1024;
    const uint32_t OA = 0, OB = 16 * 1024;
    const uint32_t smb = cvta_smem(dynsmem);
    const int wid = threadIdx.x >> 5, lane = threadIdx.x & 31;
    const int wm = wid & 1, wn = wid >> 1;
    const int NIT = Kcnt / KC;

#pragma unroll
    for (int i = 0; i < 4; i++)
#pragma unroll
        for (int j = 0; j < 8; j++)
#pragma unroll
            for (int k = 0; k < 4; k++) acc[i][j][k] = 0.0f;

    const uint32_t aPart = (uint32_t)((lane & 15) * 128 + (lane >> 4) * 16);
    const uint32_t bPart = (uint32_t)((((lane & 7) + ((lane >> 4) << 3)) * 128) + ((lane >> 3) & 1) * 16);

    // prologue: stages 0,1 -> groups 0,1
    load_tile(smb + 0 * STAGE + OA, Ah, ld, bm, 0);
    load_tile(smb + 0 * STAGE + OB, Bh, ld, bn, 0);
    cp_commit();
    load_tile(smb + 1 * STAGE + OA, Ah, ld, bm, KC);
    load_tile(smb + 1 * STAGE + OB, Bh, ld, bn, KC);
    cp_commit();

    int stg = 0, nstg = 2;
    for (int it = 0; it < NIT; ++it) {
        cp_wait<1>();
        __syncthreads();
        const uint32_t cur = smb + (uint32_t)stg * STAGE;

        uint32_t bhA[4][4], bhB[4][4];
        load_bh(cur, 0, wn, bPart, bhA);     // ks=0 B frags
        load_bh(cur, 1, wn, bPart, bhB);     // prefetch ks=1
        mma_burst(cur, 0, wm, aPart, bhA, acc);

        if (it + 2 < NIT) {                  // global loads under MMA shadow
            const uint32_t nb = smb + (uint32_t)nstg * STAGE;
            const long k0 = (long)(it + 2) * KC;
            load_tile(nb + OA, Ah, ld, bm, k0);
            load_tile(nb + OB, Bh, ld, bn, k0);
        }
        cp_commit();

        load_bh(cur, 2, wn, bPart, bhA);     // prefetch ks=2
        mma_burst(cur, 1, wm, aPart, bhB, acc);
        load_bh(cur, 3, wn, bPart, bhB);     // prefetch ks=3
        mma_burst(cur, 2, wm, aPart, bhA, acc);
        mma_burst(cur, 3, wm, aPart, bhB, acc);

        stg = (stg == 2) ? 0 : stg + 1;
        nstg = (nstg == 2) ? 0 : nstg + 1;
    }
}

// dump accs to fp32 smem stage — used only by the V-transpose epilogue
__device__ __forceinline__ void acc_to_stage(float acc[4][8][4]) {
    __syncthreads();
    float* stage = (float*)dynsmem;
    const int wid = threadIdx.x >> 5, lane = threadIdx.x & 31;
    const int wm = wid & 1, wn = wid >> 1;
    const int rl = lane >> 2, cl = (lane & 3) * 2;
#pragma unroll
    for (int mt = 0; mt < 4; ++mt)
#pragma unroll
        for (int n8 = 0; n8 < 8; ++n8) {
            const int r = wm * 64 + mt * 16 + rl;
            const int c = wn * 64 + n8 * 8 + cl;
            *(float2*)&stage[r * PITCH + c] = make_float2(acc[mt][n8][0], acc[mt][n8][1]);
            *(float2*)&stage[(r + 8) * PITCH + c] = make_float2(acc[mt][n8][2], acc[mt][n8][3]);
        }
    __syncthreads();
}

// ---------------- merged setup: convert x, convert W, zero rowsum ----------------
#define XBLKS (NELT_X / 1024)          // 16384
#define WBLKS (NELT_W / 1024)          // 3072
#define ZBLKS ((BATCH * SEQ) / 256)    // 64
__global__ void __launch_bounds__(256) setup_kernel(const float* __restrict__ x1,
                                                    const float* __restrict__ W) {
    const long b = blockIdx.x;
    if (b < XBLKS + WBLKS) {
        const float* in = (b < XBLKS) ? x1 : W;
        __half* dst = (b < XBLKS) ? g_xh : g_Wh;
        const long i = ((b < XBLKS) ? b : b - XBLKS) * 256 + threadIdx.x;
        float4 v = ((const float4*)in)[i];
        __half2 a2, b2;
        a2.x = __float2half_rn(v.x); a2.y = __float2half_rn(v.y);
        b2.x = __float2half_rn(v.z); b2.y = __float2half_rn(v.w);
        uint2 o;
        o.x = *reinterpret_cast<uint32_t*>(&a2);
        o.y = *reinterpret_cast<uint32_t*>(&b2);
        *(uint2*)(dst + i * 4) = o;
    } else {
        g_rowsum[(b - XBLKS - WBLKS) * 256 + threadIdx.x] = 0.0f;
    }
}

// ---------------- Kernel 1: QKV projection ----------------
__global__ void __launch_bounds__(128, 2) qkv_gemm_tc(const float* __restrict__ bias) {
    const long bm = (long)blockIdx.y * TM;
    const long bn = (long)blockIdx.x * TN;
    float acc[4][8][4];
    gemm1(g_xh, g_Wh, bm, bn, DIM, DIM, acc);

    const int sel = (int)(bn >> 10);        // 0:Q 1:K 2:V
    const long nc0 = bn & 1023;
    const int wid = threadIdx.x >> 5, lane = threadIdx.x & 31;
    const int wm = wid & 1, wn = wid >> 1;
    const int rl = lane >> 2, cl = (lane & 3) * 2;

    if (sel < 2) {
        __half* dst = sel ? g_Kh : g_Qh;
#pragma unroll
        for (int mt = 0; mt < 4; ++mt) {
            const long ra = bm + wm * 64 + mt * 16 + rl;
#pragma unroll
            for (int n8 = 0; n8 < 8; ++n8) {
                const int c = wn * 64 + n8 * 8 + cl;
                const float b0 = bias[bn + c], b1 = bias[bn + c + 1];
                __half2 H0, H1;
                H0.x = __float2half_rn(acc[mt][n8][0] + b0);
                H0.y = __float2half_rn(acc[mt][n8][1] + b1);
                H1.x = __float2half_rn(acc[mt][n8][2] + b0);
                H1.y = __float2half_rn(acc[mt][n8][3] + b1);
                *(__half2*)(dst + ra * DIM + nc0 + c) = H0;
                *(__half2*)(dst + (ra + 8) * DIM + nc0 + c) = H1;
            }
        }
    } else {
        acc_to_stage(acc);
        float* stage = (float*)dynsmem;
        const long b = bm >> 12, s0 = bm & 4095;
        for (int idx = threadIdx.x; idx < TM * TN; idx += 128) {
            const int row = idx & 127, col = idx >> 7;
            const float v = stage[row * PITCH + col] + bias[bn + col];
            g_Vth[(b * DIM + nc0 + col) * SEQ + s0 + row] = __float2half_rn(v);
        }
    }
}

// ---------------- Kernel 2: P̂ = exp((Q K^T)/32) — full register epilogue ----------------
__global__ void __launch_bounds__(128, 2) scores_gemm_tc() {
    const int z = blockIdx.z;
    const long bm = (long)blockIdx.y * TM;
    const long bn = (long)blockIdx.x * TN;
    const long qo = (long)z * SEQ * DIM;
    float acc[4][8][4];
    gemm1(g_Qh + qo, g_Kh + qo, bm, bn, DIM, DIM, acc);

#pragma unroll
    for (int mt = 0; mt < 4; ++mt)
#pragma unroll
        for (int n8 = 0; n8 < 8; ++n8)
#pragma unroll
            for (int k = 0; k < 4; ++k)
                acc[mt][n8][k] = __expf(acc[mt][n8][k] * 0.03125f);

    const long so = (long)z * SEQ * SEQ;
    const int wid = threadIdx.x >> 5, lane = threadIdx.x & 31;
    const int wm = wid & 1, wn = wid >> 1;
    const int rl = lane >> 2, cl = (lane & 3) * 2;
    float* rsbase = g_rowsum + (long)z * SEQ;

#pragma unroll
    for (int mt = 0; mt < 4; ++mt) {
        const long ra = bm + wm * 64 + mt * 16 + rl;
        float s0 = 0.0f, s1 = 0.0f;
#pragma unroll
        for (int n8 = 0; n8 < 8; ++n8) {
            const int c = wn * 64 + n8 * 8 + cl;
            __half2 H0, H1;
            H0.x = __float2half_rn(acc[mt][n8][0]);
            H0.y = __float2half_rn(acc[mt][n8][1]);
            H1.x = __float2half_rn(acc[mt][n8][2]);
            H1.y = __float2half_rn(acc[mt][n8][3]);
            *(__half2*)(g_Ph + so + ra * SEQ + bn + c) = H0;
            *(__half2*)(g_Ph + so + (ra + 8) * SEQ + bn + c) = H1;
            s0 += acc[mt][n8][0] + acc[mt][n8][1];
            s1 += acc[mt][n8][2] + acc[mt][n8][3];
        }
        s0 += __shfl_xor_sync(0xffffffffu, s0, 1);
        s0 += __shfl_xor_sync(0xffffffffu, s0, 2);
        s1 += __shfl_xor_sync(0xffffffffu, s1, 1);
        s1 += __shfl_xor_sync(0xffffffffu, s1, 2);
        if ((lane & 3) == 0) {
            atomicAdd(&rsbase[ra], s0);
            atomicAdd(&rsbase[ra + 8], s1);
        }
    }
}

// ---------------- Kernel 3: out = (P̂ @ V) / rowsum — register epilogue ----------------
__global__ void __launch_bounds__(128, 2) pv_gemm_tc(float* __restrict__ out) {
    const int z = blockIdx.z;
    const long bm = (long)blockIdx.y * TM;
    const long bn = (long)blockIdx.x * TN;
    const long po = (long)z * SEQ * SEQ;
    const long vo = (long)z * DIM * SEQ;
    float acc[4][8][4];
    gemm1(g_Ph + po, g_Vth + vo, bm, bn, SEQ, SEQ, acc);

    float* O = out + (long)z * SEQ * DIM;
    const float* rs = g_rowsum + (long)z * SEQ;
    const int wid = threadIdx.x >> 5, lane = threadIdx.x & 31;
    const int wm = wid & 1, wn = wid >> 1;
    const int rl = lane >> 2, cl = (lane & 3) * 2;
#pragma unroll
    for (int mt = 0; mt < 4; ++mt) {
        const long ra = bm + wm * 64 + mt * 16 + rl;
        const float ia = 1.0f / rs[ra];
        const float ib = 1.0f / rs[ra + 8];
#pragma unroll
        for (int n8 = 0; n8 < 8; ++n8) {
            const long c = bn + wn * 64 + n8 * 8 + cl;
            *(float2*)&O[ra * DIM + c] = make_float2(acc[mt][n8][0] * ia, acc[mt][n8][1] * ia);
            *(float2*)&O[(ra + 8) * DIM + c] = make_float2(acc[mt][n8][2] * ib, acc[mt][n8][3] * ib);
        }
    }
}

// ---------------------------------------------------------------------------
extern "C" void kernel_launch(void* const* d_in, const int* in_sizes, int n_in,
                              void* d_out, int out_size) {
    const float* x1 = nullptr;
    const float* W = nullptr;
    const float* bias = nullptr;
    for (int i = 0; i < n_in; i++) {
        if (in_sizes[i] == (int)(BATCH * SEQ * DIM)) x1 = (const float*)d_in[i];
        else if (in_sizes[i] == (int)(QKVN * DIM))   W = (const float*)d_in[i];
        else if (in_sizes[i] == QKVN)                bias = (const float*)d_in[i];
    }
    float* out = (float*)d_out;

    const int SM_BYTES = 96 * 1024;   // 3 x 32KB stages; fp32 stage overlay 67.6KB

    cudaFuncSetAttribute(qkv_gemm_tc, cudaFuncAttributeMaxDynamicSharedMemorySize, SM_BYTES);
    cudaFuncSetAttribute(scores_gemm_tc, cudaFuncAttributeMaxDynamicSharedMemorySize, SM_BYTES);
    cudaFuncSetAttribute(pv_gemm_tc, cudaFuncAttributeMaxDynamicSharedMemorySize, SM_BYTES);

    setup_kernel<<<XBLKS + WBLKS + ZBLKS, 256>>>(x1, W);
    qkv_gemm_tc<<<dim3(QKVN / TN, (BATCH * SEQ) / TM), 128, SM_BYTES>>>(bias);
    scores_gemm_tc<<<dim3(SEQ / TN, SEQ / TM, BATCH), 128, SM_BYTES>>>();
    pv_gemm_tc<<<dim3(DIM / TN, SEQ / TM, BATCH), 128, SM_BYTES>>>(out);
}

// round 17
// speedup vs baseline: 1.0335x; 1.0008x over previous
#include <cuda_runtime.h>
#include <cuda_fp16.h>
#include <stdint.h>

#define BATCH 4
#define SEQ   4096
#define DIM   1024
#define QKVN  3072

// CTA tile 128x128, 4 warps of 64x64, 128 threads
#define TM 128
#define TN 128
#define KC 64
#define PITCH 132   // fp32 stage pitch (V-transpose epilogue only)

#define NELT_X ((long)BATCH*SEQ*DIM)   // 16,777,216
#define NELT_W ((long)QKVN*DIM)        //  3,145,728
#define NELT_S ((long)BATCH*SEQ*SEQ)   // 67,108,864

// -------- scratch (device globals; no allocations allowed) --------
__device__ __half g_xh [NELT_X];
__device__ __half g_Wh [NELT_W];
__device__ __half g_Qh [NELT_X];
__device__ __half g_Kh [NELT_X];
__device__ __half g_Vth[NELT_X];                 // V transposed [B][DIM][SEQ]
__device__ __half g_Ph [NELT_S];                 // unnormalized exp(scores)
__device__ float  g_rowsum[(long)BATCH * SEQ];

extern __shared__ char dynsmem[];

// ---------------- helpers ----------------
__device__ __forceinline__ uint32_t cvta_smem(const void* p) {
    uint32_t a;
    asm("{ .reg .u64 t; cvta.to.shared.u64 t, %1; cvt.u32.u64 %0, t; }" : "=r"(a) : "l"(p));
    return a;
}
__device__ __forceinline__ void cp16(uint32_t s, const void* g) {
    asm volatile("cp.async.cg.shared.global [%0], [%1], 16;" :: "r"(s), "l"(g));
}
__device__ __forceinline__ void cp_commit() { asm volatile("cp.async.commit_group;" ::: "memory"); }
template <int N> __device__ __forceinline__ void cp_wait() {
    asm volatile("cp.async.wait_group %0;" :: "n"(N) : "memory");
}
__device__ __forceinline__ uint32_t swz(uint32_t off) { return off ^ ((off >> 3) & 0x70); }

__device__ __forceinline__ void ldsm4(uint32_t& r0, uint32_t& r1, uint32_t& r2, uint32_t& r3,
                                      uint32_t addr) {
    asm volatile("ldmatrix.sync.aligned.m8n8.x4.shared.b16 {%0,%1,%2,%3}, [%4];"
                 : "=r"(r0), "=r"(r1), "=r"(r2), "=r"(r3) : "r"(addr));
}
__device__ __forceinline__ void mma16816(float* c, const uint32_t* a, const uint32_t* b) {
    asm volatile(
        "mma.sync.aligned.m16n8k16.row.col.f32.f16.f16.f32 "
        "{%0,%1,%2,%3}, {%4,%5,%6,%7}, {%8,%9}, {%0,%1,%2,%3};"
        : "+f"(c[0]), "+f"(c[1]), "+f"(c[2]), "+f"(c[3])
        : "r"(a[0]), "r"(a[1]), "r"(a[2]), "r"(a[3]), "r"(b[0]), "r"(b[1]));
}

// load [128 x 64] f16 K-major tile into SW128-swizzled smem; ld = row stride (elems)
__device__ __forceinline__ void load_tile(uint32_t sb, const __half* __restrict__ src,
                                          long ld, long row0, long k0) {
    const int tid = threadIdx.x;
#pragma unroll
    for (int i = 0; i < 8; i++) {
        const int idx = tid + i * 128;        // 0..1023
        const int r = idx >> 3, ch = idx & 7;
        const uint32_t off = swz((uint32_t)(r * 128 + ch * 16));
        cp16(sb + off, src + (row0 + r) * ld + k0 + ch * 8);
    }
}

// load the 4 B fragments for one ks-step
__device__ __forceinline__ void load_bh(uint32_t cur, int ks, int wn, uint32_t bPart,
                                        uint32_t bh[4][4]) {
    const uint32_t OB = 16 * 1024;
#pragma unroll
    for (int nt = 0; nt < 4; ++nt) {
        const uint32_t off = (uint32_t)((wn * 64 + nt * 16) * 128 + ks * 32) + bPart;
        ldsm4(bh[nt][0], bh[nt][1], bh[nt][2], bh[nt][3], cur + OB + swz(off));
    }
}

// MMA burst for one ks-step with preloaded B frags and A-frag double buffering:
// ah(mt+1)'s LDSM issues before mt's 8 MMAs, so its latency hides under them.
__device__ __forceinline__ void mma_burst(uint32_t cur, int ks, int wm, uint32_t aPart,
                                          uint32_t bh[4][4], float acc[4][8][4]) {
    const uint32_t OA = 0;
    uint32_t ahC[4], ahN[4];
    {
        const uint32_t off = (uint32_t)((wm * 64) * 128 + ks * 32) + aPart;
        ldsm4(ahC[0], ahC[1], ahC[2], ahC[3], cur + OA + swz(off));
    }
#pragma unroll
    for (int mt = 0; mt < 4; ++mt) {
        if (mt < 3) {
            const uint32_t off = (uint32_t)((wm * 64 + (mt + 1) * 16) * 128 + ks * 32) + aPart;
            ldsm4(ahN[0], ahN[1], ahN[2], ahN[3], cur + OA + swz(off));
        }
#pragma unroll
        for (int nt = 0; nt < 4; ++nt) {
            mma16816(acc[mt][nt * 2],     ahC, &bh[nt][0]);
            mma16816(acc[mt][nt * 2 + 1], ahC, &bh[nt][2]);
        }
        if (mt < 3) {
            ahC[0] = ahN[0]; ahC[1] = ahN[1]; ahC[2] = ahN[2]; ahC[3] = ahN[3];
        }
    }
}

// ----------------------------------------------------------------------------
// gemm1: C[128,128] = Ah * Bh^T (single f16), 4 warps of 64x64, 3-stage pipeline.
// B fragments ping-pong across ks-steps, A fragments double-buffer within each
// burst; global loads(it+2) issue under the ks=0 MMA shadow.
// ----------------------------------------------------------------------------
__device__ __forceinline__ void gemm1(const __half* __restrict__ Ah,
                                      const __half* __restrict__ Bh,
                                      long bm, long bn, long ld, int Kcnt,
                                      float acc[4][8][4]) {
    const uint32_t STAGE = 32 * 1024;
    const uint32_t OA = 0, OB = 16 * 1024;
    const uint32_t smb = cvta_smem(dynsmem);
    const int wid = threadIdx.x >> 5, lane = threadIdx.x & 31;
    const int wm = wid & 1, wn = wid >> 1;
    const int NIT = Kcnt / KC;

#pragma unroll
    for (int i = 0; i < 4; i++)
#pragma unroll
        for (int j = 0; j < 8; j++)
#pragma unroll
            for (int k = 0; k < 4; k++) acc[i][j][k] = 0.0f;

    const uint32_t aPart = (uint32_t)((lane & 15) * 128 + (lane >> 4) * 16);
    const uint32_t bPart = (uint32_t)((((lane & 7) + ((lane >> 4) << 3)) * 128) + ((lane >> 3) & 1) * 16);

    // prologue: stages 0,1 -> groups 0,1
    load_tile(smb + 0 * STAGE + OA, Ah, ld, bm, 0);
    load_tile(smb + 0 * STAGE + OB, Bh, ld, bn, 0);
    cp_commit();
    load_tile(smb + 1 * STAGE + OA, Ah, ld, bm, KC);
    load_tile(smb + 1 * STAGE + OB, Bh, ld, bn, KC);
    cp_commit();

    int stg = 0, nstg = 2;
    for (int it = 0; it < NIT; ++it) {
        cp_wait<1>();
        __syncthreads();
        const uint32_t cur = smb + (uint32_t)stg * STAGE;

        uint32_t bhA[4][4], bhB[4][4];
        load_bh(cur, 0, wn, bPart, bhA);     // ks=0 B frags
        load_bh(cur, 1, wn, bPart, bhB);     // prefetch ks=1
        mma_burst(cur, 0, wm, aPart, bhA, acc);

        if (it + 2 < NIT) {                  // global loads under MMA shadow
            const uint32_t nb = smb + (uint32_t)nstg * STAGE;
            const long k0 = (long)(it + 2) * KC;
            load_tile(nb + OA, Ah, ld, bm, k0);
            load_tile(nb + OB, Bh, ld, bn, k0);
        }
        cp_commit();

        load_bh(cur, 2, wn, bPart, bhA);     // prefetch ks=2
        mma_burst(cur, 1, wm, aPart, bhB, acc);
        load_bh(cur, 3, wn, bPart, bhB);     // prefetch ks=3
        mma_burst(cur, 2, wm, aPart, bhA, acc);
        mma_burst(cur, 3, wm, aPart, bhB, acc);

        stg = (stg == 2) ? 0 : stg + 1;
        nstg = (nstg == 2) ? 0 : nstg + 1;
    }
}

// dump accs to fp32 smem stage — used only by the V-transpose epilogue
__device__ __forceinline__ void acc_to_stage(float acc[4][8][4]) {
    __syncthreads();
    float* stage = (float*)dynsmem;
    const int wid = threadIdx.x >> 5, lane = threadIdx.x & 31;
    const int wm = wid & 1, wn = wid >> 1;
    const int rl = lane >> 2, cl = (lane & 3) * 2;
#pragma unroll
    for (int mt = 0; mt < 4; ++mt)
#pragma unroll
        for (int n8 = 0; n8 < 8; ++n8) {
            const int r = wm * 64 + mt * 16 + rl;
            const int c = wn * 64 + n8 * 8 + cl;
            *(float2*)&stage[r * PITCH + c] = make_float2(acc[mt][n8][0], acc[mt][n8][1]);
            *(float2*)&stage[(r + 8) * PITCH + c] = make_float2(acc[mt][n8][2], acc[mt][n8][3]);
        }
    __syncthreads();
}

// ---------------- merged setup: convert x, convert W, zero rowsum ----------------
#define XBLKS (NELT_X / 1024)          // 16384
#define WBLKS (NELT_W / 1024)          // 3072
#define ZBLKS ((BATCH * SEQ) / 256)    // 64
__global__ void __launch_bounds__(256) setup_kernel(const float* __restrict__ x1,
                                                    const float* __restrict__ W) {
    const long b = blockIdx.x;
    if (b < XBLKS + WBLKS) {
        const float* in = (b < XBLKS) ? x1 : W;
        __half* dst = (b < XBLKS) ? g_xh : g_Wh;
        const long i = ((b < XBLKS) ? b : b - XBLKS) * 256 + threadIdx.x;
        float4 v = ((const float4*)in)[i];
        __half2 a2, b2;
        a2.x = __float2half_rn(v.x); a2.y = __float2half_rn(v.y);
        b2.x = __float2half_rn(v.z); b2.y = __float2half_rn(v.w);
        uint2 o;
        o.x = *reinterpret_cast<uint32_t*>(&a2);
        o.y = *reinterpret_cast<uint32_t*>(&b2);
        *(uint2*)(dst + i * 4) = o;
    } else {
        g_rowsum[(b - XBLKS - WBLKS) * 256 + threadIdx.x] = 0.0f;
    }
}

// ---------------- Kernel 1: QKV projection ----------------
__global__ void __launch_bounds__(128, 2) qkv_gemm_tc(const float* __restrict__ bias) {
    const long bm = (long)blockIdx.y * TM;
    const long bn = (long)blockIdx.x * TN;
    float acc[4][8][4];
    gemm1(g_xh, g_Wh, bm, bn, DIM, DIM, acc);

    const int sel = (int)(bn >> 10);        // 0:Q 1:K 2:V
    const long nc0 = bn & 1023;
    const int wid = threadIdx.x >> 5, lane = threadIdx.x & 31;
    const int wm = wid & 1, wn = wid >> 1;
    const int rl = lane >> 2, cl = (lane & 3) * 2;

    if (sel < 2) {
        __half* dst = sel ? g_Kh : g_Qh;
#pragma unroll
        for (int mt = 0; mt < 4; ++mt) {
            const long ra = bm + wm * 64 + mt * 16 + rl;
#pragma unroll
            for (int n8 = 0; n8 < 8; ++n8) {
                const int c = wn * 64 + n8 * 8 + cl;
                const float b0 = bias[bn + c], b1 = bias[bn + c + 1];
                __half2 H0, H1;
                H0.x = __float2half_rn(acc[mt][n8][0] + b0);
                H0.y = __float2half_rn(acc[mt][n8][1] + b1);
                H1.x = __float2half_rn(acc[mt][n8][2] + b0);
                H1.y = __float2half_rn(acc[mt][n8][3] + b1);
                *(__half2*)(dst + ra * DIM + nc0 + c) = H0;
                *(__half2*)(dst + (ra + 8) * DIM + nc0 + c) = H1;
            }
        }
    } else {
        acc_to_stage(acc);
        float* stage = (float*)dynsmem;
        const long b = bm >> 12, s0 = bm & 4095;
        for (int idx = threadIdx.x; idx < TM * TN; idx += 128) {
            const int row = idx & 127, col = idx >> 7;
            const float v = stage[row * PITCH + col] + bias[bn + col];
            g_Vth[(b * DIM + nc0 + col) * SEQ + s0 + row] = __float2half_rn(v);
        }
    }
}

// ---------------- Kernel 2: P̂ = exp((Q K^T)/32) — full register epilogue ----------------
__global__ void __launch_bounds__(128, 2) scores_gemm_tc() {
    const int z = blockIdx.z;
    const long bm = (long)blockIdx.y * TM;
    const long bn = (long)blockIdx.x * TN;
    const long qo = (long)z * SEQ * DIM;
    float acc[4][8][4];
    gemm1(g_Qh + qo, g_Kh + qo, bm, bn, DIM, DIM, acc);

#pragma unroll
    for (int mt = 0; mt < 4; ++mt)
#pragma unroll
        for (int n8 = 0; n8 < 8; ++n8)
#pragma unroll
            for (int k = 0; k < 4; ++k)
                acc[mt][n8][k] = __expf(acc[mt][n8][k] * 0.03125f);

    const long so = (long)z * SEQ * SEQ;
    const int wid = threadIdx.x >> 5, lane = threadIdx.x & 31;
    const int wm = wid & 1, wn = wid >> 1;
    const int rl = lane >> 2, cl = (lane & 3) * 2;
    float* rsbase = g_rowsum + (long)z * SEQ;

#pragma unroll
    for (int mt = 0; mt < 4; ++mt) {
        const long ra = bm + wm * 64 + mt * 16 + rl;
        float s0 = 0.0f, s1 = 0.0f;
#pragma unroll
        for (int n8 = 0; n8 < 8; ++n8) {
            const int c = wn * 64 + n8 * 8 + cl;
            __half2 H0, H1;
            H0.x = __float2half_rn(acc[mt][n8][0]);
            H0.y = __float2half_rn(acc[mt][n8][1]);
            H1.x = __float2half_rn(acc[mt][n8][2]);
            H1.y = __float2half_rn(acc[mt][n8][3]);
            *(__half2*)(g_Ph + so + ra * SEQ + bn + c) = H0;
            *(__half2*)(g_Ph + so + (ra + 8) * SEQ + bn + c) = H1;
            s0 += acc[mt][n8][0] + acc[mt][n8][1];
            s1 += acc[mt][n8][2] + acc[mt][n8][3];
        }
        s0 += __shfl_xor_sync(0xffffffffu, s0, 1);
        s0 += __shfl_xor_sync(0xffffffffu, s0, 2);
        s1 += __shfl_xor_sync(0xffffffffu, s1, 1);
        s1 += __shfl_xor_sync(0xffffffffu, s1, 2);
        if ((lane & 3) == 0) {
            atomicAdd(&rsbase[ra], s0);
            atomicAdd(&rsbase[ra + 8], s1);
        }
    }
}

// ---------------- Kernel 3: out = (P̂ @ V) / rowsum — register epilogue ----------------
__global__ void __launch_bounds__(128, 2) pv_gemm_tc(float* __restrict__ out) {
    const int z = blockIdx.z;
    const long bm = (long)blockIdx.y * TM;
    const long bn = (long)blockIdx.x * TN;
    const long po = (long)z * SEQ * SEQ;
    const long vo = (long)z * DIM * SEQ;
    float acc[4][8][4];
    gemm1(g_Ph + po, g_Vth + vo, bm, bn, SEQ, SEQ, acc);

    float* O = out + (long)z * SEQ * DIM;
    const float* rs = g_rowsum + (long)z * SEQ;
    const int wid = threadIdx.x >> 5, lane = threadIdx.x & 31;
    const int wm = wid & 1, wn = wid >> 1;
    const int rl = lane >> 2, cl = (lane & 3) * 2;
#pragma unroll
    for (int mt = 0; mt < 4; ++mt) {
        const long ra = bm + wm * 64 + mt * 16 + rl;
        const float ia = 1.0f / rs[ra];
        const float ib = 1.0f / rs[ra + 8];
#pragma unroll
        for (int n8 = 0; n8 < 8; ++n8) {
            const long c = bn + wn * 64 + n8 * 8 + cl;
            *(float2*)&O[ra * DIM + c] = make_float2(acc[mt][n8][0] * ia, acc[mt][n8][1] * ia);
            *(float2*)&O[(ra + 8) * DIM + c] = make_float2(acc[mt][n8][2] * ib, acc[mt][n8][3] * ib);
        }
    }
}

// ---------------------------------------------------------------------------
extern "C" void kernel_launch(void* const* d_in, const int* in_sizes, int n_in,
                              void* d_out, int out_size) {
    const float* x1 = nullptr;
    const float* W = nullptr;
    const float* bias = nullptr;
    for (int i = 0; i < n_in; i++) {
        if (in_sizes[i] == (int)(BATCH * SEQ * DIM)) x1 = (const float*)d_in[i];
        else if (in_sizes[i] == (int)(QKVN * DIM))   W = (const float*)d_in[i];
        else if (in_sizes[i] == QKVN)                bias = (const float*)d_in[i];
    }
    float* out = (float*)d_out;

    const int SM_BYTES = 96 * 1024;   // 3 x 32KB stages; fp32 stage overlay 67.6KB

    cudaFuncSetAttribute(qkv_gemm_tc, cudaFuncAttributeMaxDynamicSharedMemorySize, SM_BYTES);
    cudaFuncSetAttribute(scores_gemm_tc, cudaFuncAttributeMaxDynamicSharedMemorySize, SM_BYTES);
    cudaFuncSetAttribute(pv_gemm_tc, cudaFuncAttributeMaxDynamicSharedMemorySize, SM_BYTES);

    setup_kernel<<<XBLKS + WBLKS + ZBLKS, 256>>>(x1, W);
    qkv_gemm_tc<<<dim3(QKVN / TN, (BATCH * SEQ) / TM), 128, SM_BYTES>>>(bias);
    scores_gemm_tc<<<dim3(SEQ / TN, SEQ / TM, BATCH), 128, SM_BYTES>>>();
    pv_gemm_tc<<<dim3(DIM / TN, SEQ / TM, BATCH), 128, SM_BYTES>>>(out);
}